// round 15
// baseline (speedup 1.0000x reference)
#include <cuda_runtime.h>
#include <cuda_fp16.h>

#define B_    256
#define T_    4096
#define TWO_N 16
#define H_    64
#define P_    144
#define TBL   128
#define TPB   256
#define TPB1  320
#define TPERB 512            // t's per block (2 per thread)
#define NBLK  (B_*T_/TPERB)  // 2048
#define SUPB  40             // supervised-loss blocks
#define SSTR  36             // words per PAIR of stage rows (144 B)

typedef unsigned long long ull;

__device__ __forceinline__ ull pk2(float lo, float hi) {
    ull r; asm("mov.b64 %0,{%1,%2};" : "=l"(r) : "f"(lo), "f"(hi)); return r;
}
__device__ __forceinline__ float2 upk2(ull a) {
    float2 r; asm("mov.b64 {%0,%1},%2;" : "=f"(r.x), "=f"(r.y) : "l"(a)); return r;
}
__device__ __forceinline__ ull fma2(ull a, ull b, ull c) {
    ull d; asm("fma.rn.f32x2 %0,%1,%2,%3;" : "=l"(d) : "l"(a), "l"(b), "l"(c)); return d;
}
#define MINUS1_2 0xBF800000BF800000ull

// fp16 diff table (16 KB). Row r: word 2k = half2(lat,dlat), 2k+1 = deltas.
__device__ __align__(128) unsigned g_table[TBL][32];
__device__ float g_pd[NBLK];
__device__ float g_pp[NBLK];
__device__ float g_sup[SUPB];
__device__ unsigned g_fin = 0;

// ---------------------------------------------------------------------------
// Kernel 1: tabulate (R11/R12 version). Blocks 0..SUPB-1 fold sup-loss.
// ---------------------------------------------------------------------------
__global__ __launch_bounds__(TPB1) void build_table(
    const float* __restrict__ W1, const float* __restrict__ b1,
    const float* __restrict__ W2, const float* __restrict__ b2,
    const float* __restrict__ pp, const float* __restrict__ pt,
    const float* __restrict__ icp, const float* __restrict__ ict) {

    __shared__ float s_th[5][64];
    __shared__ float s_dh[5][64];
    __shared__ float s_x[5][16], s_y[5][16];
    __shared__ float s_red[8];

    const int tid = threadIdx.x;
    const int el  = tid >> 6;
    const int j   = tid & 63;
    const int e   = blockIdx.x * 4 + el;
    const bool tb = (blockIdx.x < TBL / 4);

    if (tb && e <= TBL) {
        float tv = (float)e / (float)TBL;
        float w1 = __ldg(W1 + j);
        float u  = fmaf(tv, w1, __ldg(b1 + j));
        float th = tanhf(u);
        s_th[el][j] = th;
        s_dh[el][j] = w1 * (1.f - th * th);
    }
    __syncthreads();

    {
        const int k = tid & 15;
        const int h = (tid >> 4) & 3;
        const int wi = (tid >> 5) & 1;
        float lat = 0.f, dlat = 0.f;
        if (tb && e <= TBL) {
#pragma unroll
            for (int q = 0; q < 16; q++) {
                int jj = h * 16 + q;
                float w2 = __ldg(W2 + jj * 16 + k);
                lat  = fmaf(s_th[el][jj], w2, lat);
                dlat = fmaf(s_dh[el][jj], w2, dlat);
            }
        }
        lat  += __shfl_xor_sync(0xffffffffu, lat,  16);
        dlat += __shfl_xor_sync(0xffffffffu, dlat, 16);
        if (wi == 1 && (tid & 31) < 16) { s_x[el][k] = lat; s_y[el][k] = dlat; }
        __syncthreads();
        if (tb && e <= TBL && wi == 0 && (tid & 31) < 16) {
            s_x[el][k] = lat + s_x[el][k] + __ldg(b2 + k);
            s_y[el][k] = dlat + s_y[el][k];
        }
    }
    __syncthreads();

    if (tb && tid < 64) {
        const int rr = tid >> 4, k = tid & 15;
        const int r = blockIdx.x * 4 + rr;
        if (r < TBL) {
            float v0 = s_x[rr][k],     d0 = s_y[rr][k];
            float v1 = s_x[rr + 1][k], d1 = s_y[rr + 1][k];
            __half2 hv = __floats2half2_rn(v0, d0);
            __half2 hd = __floats2half2_rn(v1 - v0, d1 - d0);
            uint2 o;
            o.x = *(unsigned*)&hv;
            o.y = *(unsigned*)&hd;
            ((uint2*)g_table[r])[k] = o;
        }
    }

    if (blockIdx.x < SUPB && tid < 256) {
        const int ebase = blockIdx.x * 1024 + tid * 4;
        float4 a, t4;
        if (ebase < B_ * P_) {
            a  = __ldg((const float4*)(pp + ebase));
            t4 = __ldg((const float4*)(pt + ebase));
        } else {
            int r = ebase - B_ * P_;
            a  = __ldg((const float4*)(icp + r));
            t4 = __ldg((const float4*)(ict + r));
        }
        float dx = a.x - t4.x, dy = a.y - t4.y, dz = a.z - t4.z, dw = a.w - t4.w;
        float s = fmaf(dx, dx, fmaf(dy, dy, fmaf(dz, dz, dw * dw)));
#pragma unroll
        for (int o = 16; o; o >>= 1) s += __shfl_down_sync(0xffffffffu, s, o);
        if ((tid & 31) == 0) s_red[tid >> 5] = s;
        __syncthreads();
        if (tid == 0) {
            float tot = 0.f;
#pragma unroll
            for (int i = 0; i < 8; i++) tot += s_red[i];
            g_sup[blockIdx.x] = tot;
        }
    }
}

// ---------------------------------------------------------------------------
// Kernel 2: main loss (exact R12 body, NO reg cap) + last-block finalize.
// ---------------------------------------------------------------------------
__global__ __launch_bounds__(TPB) void main_kernel(
    const float* __restrict__ t_in,
    const float* __restrict__ x_target,
    const float* __restrict__ params,
    float* __restrict__ out) {

    __shared__ float2 s_if[TPERB];
    __shared__ __align__(16) unsigned s_stage[TPB * SSTR];  // 36 KB
    __shared__ float s_par[P_];
    __shared__ ull   s_par2[P_];
    __shared__ float s_rd[TPB / 32], s_rp[TPB / 32];
    __shared__ int   s_flag;

    const int tid  = threadIdx.x;
    const int b    = blockIdx.x >> 3;
    const int half = blockIdx.x & 7;
    const int t0   = half * TPERB;

    // preamble
#pragma unroll
    for (int q = 0; q < 2; q++) {
        int lt = tid + q * TPB;
        float tv = __ldg(t_in + (size_t)b * T_ + t0 + lt);
        float p  = tv * (float)TBL;
        int   i  = (int)p;
        i = max(0, min(i, TBL - 1));
        float f = p - (float)i;
        __half2 f2 = __float2half2_rn(f);
        s_if[lt] = make_float2(__int_as_float(i << 7), __uint_as_float(*(unsigned*)&f2));
    }
    if (tid < P_) {
        float v = __ldg(params + (size_t)b * P_ + tid);
        s_par[tid]  = v;
        s_par2[tid] = pk2(v, v);
    }
    __syncthreads();

    // ---- Phase A: 16 passes cover 512 rows ----
    const int kk = tid & 7;
    const int ts = tid >> 3;
    const char* tbase = (const char*)g_table + kk * 16;
#pragma unroll
    for (int pass = 0; pass < 16; ++pass) {
        int r = ts + pass * 32;
        float2 v = s_if[r];
        uint4 w = __ldg((const uint4*)(tbase + __float_as_int(v.x)));
        unsigned fb = __float_as_uint(v.y);
        __half2 f2 = *(__half2*)&fb;
        __half2 r0 = __hfma2(f2, *(__half2*)&w.y, *(__half2*)&w.x);
        __half2 r1 = __hfma2(f2, *(__half2*)&w.w, *(__half2*)&w.z);
        uint2 st;
        st.x = *(unsigned*)&r0;
        st.y = *(unsigned*)&r1;
        *(uint2*)&s_stage[(r >> 1) * SSTR + (r & 1) * 16 + kk * 2] = st;
    }
    __syncthreads();

    // ---- Phase B: unpack both t's, packed f32x2 ----
    ull lat2[16], e2[8], nj2[8];
    {
        unsigned we[16], wo[16];
#pragma unroll
        for (int c = 0; c < 4; c++) {
            uint4 a = *(const uint4*)&s_stage[tid * SSTR + c * 4];
            we[c * 4 + 0] = a.x; we[c * 4 + 1] = a.y; we[c * 4 + 2] = a.z; we[c * 4 + 3] = a.w;
            uint4 o = *(const uint4*)&s_stage[tid * SSTR + 16 + c * 4];
            wo[c * 4 + 0] = o.x; wo[c * 4 + 1] = o.y; wo[c * 4 + 2] = o.z; wo[c * 4 + 3] = o.w;
        }
#pragma unroll
        for (int c = 0; c < 8; c++) {
            float2 A = __half22float2(*(__half2*)&we[c]);
            float2 Bv = __half22float2(*(__half2*)&wo[c]);
            lat2[c] = pk2(A.x, Bv.x);
            e2[c]   = pk2(A.x + A.y, Bv.x + Bv.y);
        }
#pragma unroll
        for (int c = 8; c < 16; c++) {
            float2 A = __half22float2(*(__half2*)&we[c]);
            float2 Bv = __half22float2(*(__half2*)&wo[c]);
            float muv = s_par[c];
            float sA = A.x - muv, sB = Bv.x - muv;
            lat2[c] = pk2(fmaxf(sA, 0.f), fmaxf(sB, 0.f));
            float jA = (sA > 0.f) ? A.y : 0.f;
            float jB = (sB > 0.f) ? Bv.y : 0.f;
            nj2[c - 8] = pk2(-jA, -jB);
        }
    }

    ull accp = 0ull;
#pragma unroll
    for (int k = 0; k < 8; k++) {
        ull pix = fma2(e2[k], MINUS1_2, s_par2[k]);
#pragma unroll
        for (int j = 0; j < 8; j++)
            pix = fma2(s_par2[16 + k * 8 + j], lat2[8 + j], pix);
        accp = fma2(pix, pix, accp);
        ull m2 = fma2(lat2[8 + k], MINUS1_2, s_par2[8 + k]);
        ull ga = 0ull;
#pragma unroll
        for (int j = 0; j < 8; j++)
            ga = fma2(s_par2[80 + k * 8 + j], lat2[j], ga);
        ull dd = fma2(ga, m2, nj2[k]);
        accp = fma2(dd, dd, accp);
    }

    ull accd = 0ull;
    const ull* xt = (const ull*)(x_target + (size_t)b * TWO_N * T_ + t0 + 2 * tid);
#pragma unroll
    for (int k = 0; k < 16; k++) {
        ull v = __ldg(xt + (size_t)k * (T_ / 2));
        ull d = fma2(v, MINUS1_2, lat2[k]);
        accd = fma2(d, d, accd);
    }

    // ---- block reduction ----
    float2 ap = upk2(accp), ad = upk2(accd);
    float acc_p = ap.x + ap.y;
    float acc_d = ad.x + ad.y;
#pragma unroll
    for (int o = 16; o; o >>= 1) {
        acc_d += __shfl_down_sync(0xffffffffu, acc_d, o);
        acc_p += __shfl_down_sync(0xffffffffu, acc_p, o);
    }
    const int lane = tid & 31, wid = tid >> 5;
    if (lane == 0) { s_rd[wid] = acc_d; s_rp[wid] = acc_p; }
    __syncthreads();
    if (tid == 0) {
        float sd = 0.f, sp = 0.f;
#pragma unroll
        for (int i = 0; i < TPB / 32; i++) { sd += s_rd[i]; sp += s_rp[i]; }
        g_pd[blockIdx.x] = sd;
        g_pp[blockIdx.x] = sp;
        __threadfence();
        unsigned old = atomicAdd(&g_fin, 1u);
        s_flag = (old == NBLK - 1);
    }
    __syncthreads();

    // ---- last block: deterministic finalize + counter reset ----
    if (s_flag) {
        double sd = 0.0, sp = 0.0;
        for (int i = tid; i < NBLK; i += TPB) {
            sd += (double)g_pd[i];
            sp += (double)g_pp[i];
        }
        double ss = (tid < SUPB) ? (double)g_sup[tid] : 0.0;
        double* r1 = (double*)s_stage;
        double* r2 = r1 + TPB;
        double* r3 = r2 + TPB;
        r1[tid] = sd; r2[tid] = sp; r3[tid] = ss;
        __syncthreads();
        for (int o = 128; o; o >>= 1) {
            if (tid < o) { r1[tid] += r1[tid + o]; r2[tid] += r2[tid + o]; r3[tid] += r3[tid + o]; }
            __syncthreads();
        }
        if (tid == 0) {
            double res = (r1[0] + r2[0]) / 16777216.0 + r3[0] / 40960.0;
            out[0] = (float)res;
            g_fin = 0;
        }
    }
}

// ---------------------------------------------------------------------------
extern "C" void kernel_launch(void* const* d_in, const int* in_sizes, int n_in,
                              void* d_out, int out_size) {
    const float* t   = (const float*)d_in[0];
    const float* xt  = (const float*)d_in[1];
    const float* pp  = (const float*)d_in[2];
    const float* pt  = (const float*)d_in[3];
    const float* icp = (const float*)d_in[4];
    const float* ict = (const float*)d_in[5];
    const float* W1  = (const float*)d_in[6];
    const float* b1  = (const float*)d_in[7];
    const float* W2  = (const float*)d_in[8];
    const float* b2  = (const float*)d_in[9];

    build_table<<<SUPB, TPB1>>>(W1, b1, W2, b2, pp, pt, icp, ict);
    main_kernel<<<NBLK, TPB>>>(t, xt, pp, (float*)d_out);
}

// round 16
// speedup vs baseline: 1.0885x; 1.0885x over previous
#include <cuda_runtime.h>
#include <cuda_fp16.h>

#define B_    256
#define T_    4096
#define TWO_N 16
#define H_    64
#define P_    144
#define TBL   128
#define TPB   256
#define TPB1  320
#define TPERB 512            // t's per block (2 per thread)
#define NBLK  (B_*T_/TPERB)  // 2048
#define SUPB  40             // supervised-loss blocks
#define SSTR  36             // words per PAIR of stage rows (144 B)

typedef unsigned long long ull;

__device__ __forceinline__ ull pk2(float lo, float hi) {
    ull r; asm("mov.b64 %0,{%1,%2};" : "=l"(r) : "f"(lo), "f"(hi)); return r;
}
__device__ __forceinline__ float2 upk2(ull a) {
    float2 r; asm("mov.b64 {%0,%1},%2;" : "=f"(r.x), "=f"(r.y) : "l"(a)); return r;
}
__device__ __forceinline__ ull fma2(ull a, ull b, ull c) {
    ull d; asm("fma.rn.f32x2 %0,%1,%2,%3;" : "=l"(d) : "l"(a), "l"(b), "l"(c)); return d;
}
__device__ __forceinline__ ull add2(ull a, ull b) {
    ull d; asm("add.rn.f32x2 %0,%1,%2;" : "=l"(d) : "l"(a), "l"(b)); return d;
}
#define MINUS1_2 0xBF800000BF800000ull

// fp16 diff table (16 KB). Row r: word 2k = half2(lat,dlat), 2k+1 = deltas.
__device__ __align__(128) unsigned g_table[TBL][32];
__device__ float g_pd[NBLK];
__device__ float g_pp[NBLK];
__device__ float g_sup[SUPB];
__device__ unsigned g_fin = 0;

// ---------------------------------------------------------------------------
// Kernel 1: tabulate (R11/R12 version). Blocks 0..SUPB-1 fold sup-loss.
// ---------------------------------------------------------------------------
__global__ __launch_bounds__(TPB1) void build_table(
    const float* __restrict__ W1, const float* __restrict__ b1,
    const float* __restrict__ W2, const float* __restrict__ b2,
    const float* __restrict__ pp, const float* __restrict__ pt,
    const float* __restrict__ icp, const float* __restrict__ ict) {

    __shared__ float s_th[5][64];
    __shared__ float s_dh[5][64];
    __shared__ float s_x[5][16], s_y[5][16];
    __shared__ float s_red[8];

    const int tid = threadIdx.x;
    const int el  = tid >> 6;
    const int j   = tid & 63;
    const int e   = blockIdx.x * 4 + el;
    const bool tb = (blockIdx.x < TBL / 4);

    if (tb && e <= TBL) {
        float tv = (float)e / (float)TBL;
        float w1 = __ldg(W1 + j);
        float u  = fmaf(tv, w1, __ldg(b1 + j));
        float th = tanhf(u);
        s_th[el][j] = th;
        s_dh[el][j] = w1 * (1.f - th * th);
    }
    __syncthreads();

    {
        const int k = tid & 15;
        const int h = (tid >> 4) & 3;
        const int wi = (tid >> 5) & 1;
        float lat = 0.f, dlat = 0.f;
        if (tb && e <= TBL) {
#pragma unroll
            for (int q = 0; q < 16; q++) {
                int jj = h * 16 + q;
                float w2 = __ldg(W2 + jj * 16 + k);
                lat  = fmaf(s_th[el][jj], w2, lat);
                dlat = fmaf(s_dh[el][jj], w2, dlat);
            }
        }
        lat  += __shfl_xor_sync(0xffffffffu, lat,  16);
        dlat += __shfl_xor_sync(0xffffffffu, dlat, 16);
        if (wi == 1 && (tid & 31) < 16) { s_x[el][k] = lat; s_y[el][k] = dlat; }
        __syncthreads();
        if (tb && e <= TBL && wi == 0 && (tid & 31) < 16) {
            s_x[el][k] = lat + s_x[el][k] + __ldg(b2 + k);
            s_y[el][k] = dlat + s_y[el][k];
        }
    }
    __syncthreads();

    if (tb && tid < 64) {
        const int rr = tid >> 4, k = tid & 15;
        const int r = blockIdx.x * 4 + rr;
        if (r < TBL) {
            float v0 = s_x[rr][k],     d0 = s_y[rr][k];
            float v1 = s_x[rr + 1][k], d1 = s_y[rr + 1][k];
            __half2 hv = __floats2half2_rn(v0, d0);
            __half2 hd = __floats2half2_rn(v1 - v0, d1 - d0);
            uint2 o;
            o.x = *(unsigned*)&hv;
            o.y = *(unsigned*)&hd;
            ((uint2*)g_table[r])[k] = o;
        }
    }

    if (blockIdx.x < SUPB && tid < 256) {
        const int ebase = blockIdx.x * 1024 + tid * 4;
        float4 a, t4;
        if (ebase < B_ * P_) {
            a  = __ldg((const float4*)(pp + ebase));
            t4 = __ldg((const float4*)(pt + ebase));
        } else {
            int r = ebase - B_ * P_;
            a  = __ldg((const float4*)(icp + r));
            t4 = __ldg((const float4*)(ict + r));
        }
        float dx = a.x - t4.x, dy = a.y - t4.y, dz = a.z - t4.z, dw = a.w - t4.w;
        float s = fmaf(dx, dx, fmaf(dy, dy, fmaf(dz, dz, dw * dw)));
#pragma unroll
        for (int o = 16; o; o >>= 1) s += __shfl_down_sync(0xffffffffu, s, o);
        if ((tid & 31) == 0) s_red[tid >> 5] = s;
        __syncthreads();
        if (tid == 0) {
            float tot = 0.f;
#pragma unroll
            for (int i = 0; i < 8; i++) tot += s_red[i];
            g_sup[blockIdx.x] = tot;
        }
    }
}

// ---------------------------------------------------------------------------
// Kernel 2: main loss (R12 body, dual accumulators) + last-block finalize.
// __launch_bounds__(TPB, 3): regs <= 85 — above hot path's natural 78
// (no hot spills), below the 94 the fused epilogue would otherwise take.
// ---------------------------------------------------------------------------
__global__ __launch_bounds__(TPB, 3) void main_kernel(
    const float* __restrict__ t_in,
    const float* __restrict__ x_target,
    const float* __restrict__ params,
    float* __restrict__ out) {

    __shared__ float2 s_if[TPERB];
    __shared__ __align__(16) unsigned s_stage[TPB * SSTR];  // 36 KB
    __shared__ float s_par[P_];
    __shared__ ull   s_par2[P_];
    __shared__ float s_rd[TPB / 32], s_rp[TPB / 32];
    __shared__ int   s_flag;

    const int tid  = threadIdx.x;
    const int b    = blockIdx.x >> 3;
    const int half = blockIdx.x & 7;
    const int t0   = half * TPERB;

    // preamble
#pragma unroll
    for (int q = 0; q < 2; q++) {
        int lt = tid + q * TPB;
        float tv = __ldg(t_in + (size_t)b * T_ + t0 + lt);
        float p  = tv * (float)TBL;
        int   i  = (int)p;
        i = max(0, min(i, TBL - 1));
        float f = p - (float)i;
        __half2 f2 = __float2half2_rn(f);
        s_if[lt] = make_float2(__int_as_float(i << 7), __uint_as_float(*(unsigned*)&f2));
    }
    if (tid < P_) {
        float v = __ldg(params + (size_t)b * P_ + tid);
        s_par[tid]  = v;
        s_par2[tid] = pk2(v, v);
    }
    __syncthreads();

    // ---- Phase A: 16 passes cover 512 rows ----
    const int kk = tid & 7;
    const int ts = tid >> 3;
    const char* tbase = (const char*)g_table + kk * 16;
#pragma unroll
    for (int pass = 0; pass < 16; ++pass) {
        int r = ts + pass * 32;
        float2 v = s_if[r];
        uint4 w = __ldg((const uint4*)(tbase + __float_as_int(v.x)));
        unsigned fb = __float_as_uint(v.y);
        __half2 f2 = *(__half2*)&fb;
        __half2 r0 = __hfma2(f2, *(__half2*)&w.y, *(__half2*)&w.x);
        __half2 r1 = __hfma2(f2, *(__half2*)&w.w, *(__half2*)&w.z);
        uint2 st;
        st.x = *(unsigned*)&r0;
        st.y = *(unsigned*)&r1;
        *(uint2*)&s_stage[(r >> 1) * SSTR + (r & 1) * 16 + kk * 2] = st;
    }
    __syncthreads();

    // ---- Phase B: unpack both t's, packed f32x2 ----
    ull lat2[16], e2[8], nj2[8];
    {
        unsigned we[16], wo[16];
#pragma unroll
        for (int c = 0; c < 4; c++) {
            uint4 a = *(const uint4*)&s_stage[tid * SSTR + c * 4];
            we[c * 4 + 0] = a.x; we[c * 4 + 1] = a.y; we[c * 4 + 2] = a.z; we[c * 4 + 3] = a.w;
            uint4 o = *(const uint4*)&s_stage[tid * SSTR + 16 + c * 4];
            wo[c * 4 + 0] = o.x; wo[c * 4 + 1] = o.y; wo[c * 4 + 2] = o.z; wo[c * 4 + 3] = o.w;
        }
#pragma unroll
        for (int c = 0; c < 8; c++) {
            float2 A = __half22float2(*(__half2*)&we[c]);
            float2 Bv = __half22float2(*(__half2*)&wo[c]);
            lat2[c] = pk2(A.x, Bv.x);
            e2[c]   = pk2(A.x + A.y, Bv.x + Bv.y);
        }
#pragma unroll
        for (int c = 8; c < 16; c++) {
            float2 A = __half22float2(*(__half2*)&we[c]);
            float2 Bv = __half22float2(*(__half2*)&wo[c]);
            float muv = s_par[c];
            float sA = A.x - muv, sB = Bv.x - muv;
            lat2[c] = pk2(fmaxf(sA, 0.f), fmaxf(sB, 0.f));
            float jA = (sA > 0.f) ? A.y : 0.f;
            float jB = (sB > 0.f) ? Bv.y : 0.f;
            nj2[c - 8] = pk2(-jA, -jB);
        }
    }

    // physics loss: dual accumulators (even/odd k) to halve the chain depth
    ull accp0 = 0ull, accp1 = 0ull;
#pragma unroll
    for (int k = 0; k < 8; k++) {
        ull pix = fma2(e2[k], MINUS1_2, s_par2[k]);
#pragma unroll
        for (int j = 0; j < 8; j++)
            pix = fma2(s_par2[16 + k * 8 + j], lat2[8 + j], pix);
        ull m2 = fma2(lat2[8 + k], MINUS1_2, s_par2[8 + k]);
        ull ga = 0ull;
#pragma unroll
        for (int j = 0; j < 8; j++)
            ga = fma2(s_par2[80 + k * 8 + j], lat2[j], ga);
        ull dd = fma2(ga, m2, nj2[k]);
        if (k & 1) { accp1 = fma2(pix, pix, accp1); accp1 = fma2(dd, dd, accp1); }
        else       { accp0 = fma2(pix, pix, accp0); accp0 = fma2(dd, dd, accp0); }
    }

    // data loss: dual accumulators
    ull accd0 = 0ull, accd1 = 0ull;
    const ull* xt = (const ull*)(x_target + (size_t)b * TWO_N * T_ + t0 + 2 * tid);
#pragma unroll
    for (int k = 0; k < 16; k++) {
        ull v = __ldg(xt + (size_t)k * (T_ / 2));
        ull d = fma2(v, MINUS1_2, lat2[k]);
        if (k & 1) accd1 = fma2(d, d, accd1);
        else       accd0 = fma2(d, d, accd0);
    }

    // ---- block reduction ----
    float2 ap = upk2(add2(accp0, accp1)), ad = upk2(add2(accd0, accd1));
    float acc_p = ap.x + ap.y;
    float acc_d = ad.x + ad.y;
#pragma unroll
    for (int o = 16; o; o >>= 1) {
        acc_d += __shfl_down_sync(0xffffffffu, acc_d, o);
        acc_p += __shfl_down_sync(0xffffffffu, acc_p, o);
    }
    const int lane = tid & 31, wid = tid >> 5;
    if (lane == 0) { s_rd[wid] = acc_d; s_rp[wid] = acc_p; }
    __syncthreads();
    if (tid == 0) {
        float sd = 0.f, sp = 0.f;
#pragma unroll
        for (int i = 0; i < TPB / 32; i++) { sd += s_rd[i]; sp += s_rp[i]; }
        g_pd[blockIdx.x] = sd;
        g_pp[blockIdx.x] = sp;
        __threadfence();
        unsigned old = atomicAdd(&g_fin, 1u);
        s_flag = (old == NBLK - 1);
    }
    __syncthreads();

    // ---- last block: deterministic finalize + counter reset ----
    if (s_flag) {
        double sd = 0.0, sp = 0.0;
        for (int i = tid; i < NBLK; i += TPB) {
            sd += (double)g_pd[i];
            sp += (double)g_pp[i];
        }
        double ss = (tid < SUPB) ? (double)g_sup[tid] : 0.0;
        double* r1 = (double*)s_stage;
        double* r2 = r1 + TPB;
        double* r3 = r2 + TPB;
        r1[tid] = sd; r2[tid] = sp; r3[tid] = ss;
        __syncthreads();
        for (int o = 128; o; o >>= 1) {
            if (tid < o) { r1[tid] += r1[tid + o]; r2[tid] += r2[tid + o]; r3[tid] += r3[tid + o]; }
            __syncthreads();
        }
        if (tid == 0) {
            double res = (r1[0] + r2[0]) / 16777216.0 + r3[0] / 40960.0;
            out[0] = (float)res;
            g_fin = 0;
        }
    }
}

// ---------------------------------------------------------------------------
extern "C" void kernel_launch(void* const* d_in, const int* in_sizes, int n_in,
                              void* d_out, int out_size) {
    const float* t   = (const float*)d_in[0];
    const float* xt  = (const float*)d_in[1];
    const float* pp  = (const float*)d_in[2];
    const float* pt  = (const float*)d_in[3];
    const float* icp = (const float*)d_in[4];
    const float* ict = (const float*)d_in[5];
    const float* W1  = (const float*)d_in[6];
    const float* b1  = (const float*)d_in[7];
    const float* W2  = (const float*)d_in[8];
    const float* b2  = (const float*)d_in[9];

    build_table<<<SUPB, TPB1>>>(W1, b1, W2, b2, pp, pt, icp, ict);
    main_kernel<<<NBLK, TPB>>>(t, xt, pp, (float*)d_out);
}